// round 10
// baseline (speedup 1.0000x reference)
#include <cuda_runtime.h>
#include <cuda_fp16.h>
#include <cstdint>

// ---------------------------------------------------------------------------
// EdgeDecoder:
//   A'[n] = z[n] @ W1[0:128,:] + b1 ; B[n] = z[n] @ W1[128:256,:]
//   score[e] = relu(A'[src] + B[dst]) . W2 + b2
//
// R10: edge kernel is at the L2/LTS byte cap (R6: 819MB -> 73.6us == cap).
// Build CSR by src (hist+scan+scatter). Warp owns one src: A' read ONCE into
// regs (25.6MB total instead of 410MB); B stays gathered. Inner math = R6.
// gemm/prep unchanged (R8).
// ---------------------------------------------------------------------------

#define HID 128
#define N_MAX 100000
#define E_MAX 1600000
#define NS_PAD 100352            // 196 * 512
#define NPART 196

__device__ __align__(16) __half g_AB[(size_t)N_MAX * 256];
__device__ __align__(16) __half g_Whi[128 * 256];
__device__ int g_is64;
__device__ int g_hist[NS_PAD];
__device__ int g_rowstart[NS_PAD];
__device__ int g_cursor[NS_PAD];
__device__ int g_part[NPART];
__device__ __align__(8) uint2 g_elist[E_MAX];

// ---- tensor-core primitives ----
__device__ __forceinline__ void ldsm4(unsigned* r, const void* p) {
    unsigned a = (unsigned)__cvta_generic_to_shared(p);
    asm volatile("ldmatrix.sync.aligned.m8n8.x4.shared.b16 {%0,%1,%2,%3},[%4];"
                 : "=r"(r[0]), "=r"(r[1]), "=r"(r[2]), "=r"(r[3]) : "r"(a));
}
__device__ __forceinline__ void ldsm2t(unsigned* r, const void* p) {
    unsigned a = (unsigned)__cvta_generic_to_shared(p);
    asm volatile("ldmatrix.sync.aligned.m8n8.x2.trans.shared.b16 {%0,%1},[%2];"
                 : "=r"(r[0]), "=r"(r[1]) : "r"(a));
}
__device__ __forceinline__ void stsm4(void* p, unsigned r0, unsigned r1,
                                      unsigned r2, unsigned r3) {
    unsigned a = (unsigned)__cvta_generic_to_shared(p);
    asm volatile("stmatrix.sync.aligned.m8n8.x4.shared.b16 [%0],{%1,%2,%3,%4};"
                 :: "r"(a), "r"(r0), "r"(r1), "r"(r2), "r"(r3));
}
__device__ __forceinline__ void mma16816(float* c, const unsigned* a, const unsigned* b) {
    asm volatile(
        "mma.sync.aligned.m16n8k16.row.col.f32.f16.f16.f32 "
        "{%0,%1,%2,%3},{%4,%5,%6,%7},{%8,%9},{%0,%1,%2,%3};"
        : "+f"(c[0]), "+f"(c[1]), "+f"(c[2]), "+f"(c[3])
        : "r"(a[0]), "r"(a[1]), "r"(a[2]), "r"(a[3]), "r"(b[0]), "r"(b[1]));
}

#define ZS 136
#define WS 264
#define OS 264
#define MTILE 64
#define SMEM_BYTES ((128 * WS + 2 * MTILE * ZS) * 2)   // 102,400 B

// ---------------------------------------------------------------------------
// Prep: W fp16 cvt + dtype probe + zero hist. grid 256 x 512.
// ---------------------------------------------------------------------------
__global__ __launch_bounds__(512) void prep_w(
    const float* __restrict__ W1, const int* __restrict__ ei32)
{
    int idx = blockIdx.x * 512 + threadIdx.x;
    if (blockIdx.x == 0 && threadIdx.x == 0) {
        int all0 = 1;
#pragma unroll
        for (int i = 0; i < 8; ++i) all0 &= (ei32[2 * i + 1] == 0);
        g_is64 = all0;
    }
    if (idx < 32768) {
        int k = idx >> 8, j = idx & 255;
        float f = (j < 128) ? W1[(size_t)k * 128 + j]
                            : W1[(size_t)(128 + k) * 128 + (j - 128)];
        g_Whi[idx] = __float2half_rn(f);
    }
    if (idx < NS_PAD) g_hist[idx] = 0;
}

// ---------------------------------------------------------------------------
// CSR build chain.
// ---------------------------------------------------------------------------
__global__ __launch_bounds__(512) void hist_k(
    const void* __restrict__ ei_raw, int E, int N)
{
    int e = blockIdx.x * 512 + threadIdx.x;
    if (e >= E) return;
    const int* p = (const int*)ei_raw;
    unsigned s = g_is64 ? (unsigned)p[2 * (size_t)e] : (unsigned)p[e];
    s = min(s, (unsigned)(N - 1));
    atomicAdd(&g_hist[s], 1);
}

__global__ __launch_bounds__(512) void scan1_k()
{
    __shared__ int sh[512];
    const int t = threadIdx.x;
    const int i = blockIdx.x * 512 + t;
    int v = g_hist[i];
    sh[t] = v;
    __syncthreads();
#pragma unroll
    for (int off = 1; off < 512; off <<= 1) {
        int x = sh[t];
        if (t >= off) x += sh[t - off];
        __syncthreads();
        sh[t] = x;
        __syncthreads();
    }
    g_rowstart[i] = sh[t] - v;           // exclusive within block
    if (t == 511) g_part[blockIdx.x] = sh[511];
}

__global__ __launch_bounds__(256) void scan2_k()
{
    __shared__ int sh[256];
    const int t = threadIdx.x;
    int v = (t < NPART) ? g_part[t] : 0;
    sh[t] = v;
    __syncthreads();
#pragma unroll
    for (int off = 1; off < 256; off <<= 1) {
        int x = sh[t];
        if (t >= off) x += sh[t - off];
        __syncthreads();
        sh[t] = x;
        __syncthreads();
    }
    if (t < NPART) g_part[t] = sh[t] - v;  // exclusive
}

__global__ __launch_bounds__(512) void scan3_k()
{
    const int i = blockIdx.x * 512 + threadIdx.x;
    int r = g_rowstart[i] + g_part[blockIdx.x];
    g_rowstart[i] = r;
    g_cursor[i] = r;
}

__global__ __launch_bounds__(512) void scatter_k(
    const void* __restrict__ ei_raw, int E, int N)
{
    int e = blockIdx.x * 512 + threadIdx.x;
    if (e >= E) return;
    const int* p = (const int*)ei_raw;
    unsigned s, d;
    if (g_is64) {
        s = (unsigned)p[2 * (size_t)e];
        d = (unsigned)p[2 * ((size_t)E + e)];
    } else {
        s = (unsigned)p[e];
        d = (unsigned)p[(size_t)E + e];
    }
    s = min(s, (unsigned)(N - 1));
    d = min(d, (unsigned)(N - 1));
    int pos = atomicAdd(&g_cursor[s], 1);
    g_elist[pos] = make_uint2(d * 256u + 128u, (unsigned)e);
}

// ---------------------------------------------------------------------------
// Persistent GEMM (R8 verbatim): M-tile 64, 2 CTAs/SM, 2-term compensated.
// ---------------------------------------------------------------------------
__global__ __launch_bounds__(512, 2) void gemm_tc(
    const float* __restrict__ z, const float* __restrict__ b1,
    int N, int nstrips)
{
    extern __shared__ __align__(16) char dynsmem[];
    __half* Whi = (__half*)dynsmem;            // [128][WS]
    __half* Zhi = Whi + 128 * WS;              // [MTILE][ZS]
    __half* Zlo = Zhi + MTILE * ZS;
    __half* Stage = Zhi;                       // overlay [MTILE][OS]

    const int t    = threadIdx.x;
    const int lane = t & 31;
    const int w    = t >> 5;

#pragma unroll
    for (int i = 0; i < 8; ++i) {
        int idx = t + i * 512;
        int row = idx >> 5, c16 = idx & 31;
        *(uint4*)&Whi[row * WS + c16 * 8] = *(const uint4*)&g_Whi[row * 256 + c16 * 8];
    }
    __syncthreads();

    const int wm = w >> 3, wn = w & 7;
    const int mbase = wm * 32, nbase = wn * 32;
    const int arow = lane & 15, acol8 = (lane >> 4) << 3;
    const int brow = lane & 15;

    float bx[4], by[4];
#pragma unroll
    for (int nt = 0; nt < 4; ++nt) {
        int col = nbase + nt * 8 + (lane & 3) * 2;
        bx[nt] = (wn < 4) ? __ldg(b1 + col)     : 0.f;
        by[nt] = (wn < 4) ? __ldg(b1 + col + 1) : 0.f;
    }

    for (int strip = blockIdx.x; strip < nstrips; strip += gridDim.x) {
        const int row0 = strip * MTILE;

#pragma unroll
        for (int i = 0; i < 4; ++i) {
            int idx4 = t + i * 512;
            int r = idx4 >> 5, c = (idx4 & 31) * 4;
            int gr = row0 + r; if (gr >= N) gr = N - 1;
            float4 v = *(const float4*)(z + (size_t)gr * HID + c);
            __half2 h0 = __floats2half2_rn(v.x, v.y);
            __half2 h1 = __floats2half2_rn(v.z, v.w);
            float2 f0 = __half22float2(h0), f1 = __half22float2(h1);
            __half2 l0 = __floats2half2_rn(v.x - f0.x, v.y - f0.y);
            __half2 l1 = __floats2half2_rn(v.z - f1.x, v.w - f1.y);
            uint2 sh, sl;
            sh.x = *(unsigned*)&h0; sh.y = *(unsigned*)&h1;
            sl.x = *(unsigned*)&l0; sl.y = *(unsigned*)&l1;
            *(uint2*)&Zhi[r * ZS + c] = sh;
            *(uint2*)&Zlo[r * ZS + c] = sl;
        }
        __syncthreads();

        float acc[2][4][4];
#pragma unroll
        for (int mt = 0; mt < 2; ++mt)
#pragma unroll
            for (int nt = 0; nt < 4; ++nt)
#pragma unroll
                for (int q = 0; q < 4; ++q) acc[mt][nt][q] = 0.f;

#pragma unroll
        for (int ks = 0; ks < 8; ++ks) {
            const int k0 = ks * 16;
            unsigned ah[2][4], al[2][4];
#pragma unroll
            for (int mt = 0; mt < 2; ++mt) {
                const int rr = (mbase + mt * 16 + arow) * ZS + k0 + acol8;
                ldsm4(ah[mt], Zhi + rr);
                ldsm4(al[mt], Zlo + rr);
            }
#pragma unroll
            for (int nt = 0; nt < 4; ++nt) {
                unsigned bb[2];
                const int wr = (k0 + brow) * WS + nbase + nt * 8;
                ldsm2t(bb, Whi + wr);
#pragma unroll
                for (int mt = 0; mt < 2; ++mt) {
                    mma16816(acc[mt][nt], ah[mt], bb);
                    mma16816(acc[mt][nt], al[mt], bb);
                }
            }
        }
        __syncthreads();

        const int stile = lane >> 3;
        const int srow  = lane & 7;
#pragma unroll
        for (int mt = 0; mt < 2; ++mt) {
            __half2 u[4], l[4];
#pragma unroll
            for (int nt = 0; nt < 4; ++nt) {
                u[nt] = __floats2half2_rn(acc[mt][nt][0] + bx[nt], acc[mt][nt][1] + by[nt]);
                l[nt] = __floats2half2_rn(acc[mt][nt][2] + bx[nt], acc[mt][nt][3] + by[nt]);
            }
            __half* pu = Stage + (mbase + mt * 16 + srow) * OS + nbase + stile * 8;
            __half* pl = Stage + (mbase + mt * 16 + 8 + srow) * OS + nbase + stile * 8;
            stsm4(pu, *(unsigned*)&u[0], *(unsigned*)&u[1], *(unsigned*)&u[2], *(unsigned*)&u[3]);
            stsm4(pl, *(unsigned*)&l[0], *(unsigned*)&l[1], *(unsigned*)&l[2], *(unsigned*)&l[3]);
        }
        __syncthreads();

#pragma unroll
        for (int i = 0; i < 4; ++i) {
            int idx = t + i * 512;
            int r = idx >> 5, c16 = idx & 31;
            int gr = row0 + r;
            if (gr < N) {
                uint4 v = *(const uint4*)&Stage[r * OS + c16 * 8];
                *(uint4*)&g_AB[(size_t)gr * 256 + c16 * 8] = v;
            }
        }
        __syncthreads();
    }
}

// ---------------------------------------------------------------------------
// CSR edge kernel: warp owns one src. A' in regs; B gathered; R6 inner math.
// 16-lane groups process 2 edges/iter; all lanes stay converged for shfl.
// ---------------------------------------------------------------------------
__global__ __launch_bounds__(256) void edge_csr(
    const float* __restrict__ W2,
    const float* __restrict__ b2,
    float* __restrict__ out,
    int E, int N)
{
    const int lane = threadIdx.x & 31;
    const int gl   = lane & 15;
    const int hi16 = lane >> 4;
    const int warp = threadIdx.x >> 5;

    const float4 wwl = *(const float4*)(W2 + gl * 8);
    const float4 wwh = *(const float4*)(W2 + gl * 8 + 4);
    const float wwf[8] = {wwl.x, wwl.y, wwl.z, wwl.w, wwh.x, wwh.y, wwh.z, wwh.w};
    const float bias2 = __ldg(b2);
    const __half2 zero2 = __float2half2_rn(0.f);

    const int gw = blockIdx.x * 8 + warp;
    const int nw = gridDim.x * 8;

    for (int s = gw; s < N; s += nw) {
        const int start = g_rowstart[s];
        const int deg   = g_hist[s];
        if (deg == 0) continue;

        const uint4 ar = *(const uint4*)(g_AB + (size_t)s * 256 + gl * 8);
        const unsigned* au = (const unsigned*)&ar;

        const int iters = (deg + 1) >> 1;
        for (int it = 0; it < iters; ++it) {
            const int j = it * 2 + hi16;
            const bool ok = (j < deg);
            uint2 ent = make_uint2(0u, 0u);
            float sum = 0.f;
            if (ok) {
                ent = g_elist[start + j];
                const uint4 br = *(const uint4*)(g_AB + ent.x + gl * 8);
                const unsigned* bu = (const unsigned*)&br;
#pragma unroll
                for (int i = 0; i < 4; ++i) {
                    __half2 r = __hmax2(__hadd2(*(const __half2*)&au[i],
                                                *(const __half2*)&bu[i]), zero2);
                    float2 f = __half22float2(r);
                    sum = fmaf(f.x, wwf[2 * i],     sum);
                    sum = fmaf(f.y, wwf[2 * i + 1], sum);
                }
            }
#pragma unroll
            for (int off = 8; off; off >>= 1)
                sum += __shfl_xor_sync(0xFFFFFFFFu, sum, off);

            if (gl == 0 && ok)
                out[ent.y] = sum + bias2;
        }
    }
}

// ---------------------------------------------------------------------------
extern "C" void kernel_launch(void* const* d_in, const int* in_sizes, int n_in,
                              void* d_out, int out_size)
{
    const float* z   = (const float*)d_in[0];
    const void*  ei  = d_in[1];
    const float* W1  = (const float*)d_in[2];
    const float* b1  = (const float*)d_in[3];
    const float* W2  = (const float*)d_in[4];
    const float* b2  = (const float*)d_in[5];
    float*       out = (float*)d_out;

    const int N = in_sizes[0] / HID;   // 100000
    const int E = in_sizes[1] / 2;     // 1600000

    static int smem_set = 0;
    if (!smem_set) {
        cudaFuncSetAttribute(gemm_tc, cudaFuncAttributeMaxDynamicSharedMemorySize,
                             SMEM_BYTES);
        smem_set = 1;
    }

    // prep (W cvt + probe + zero hist)
    prep_w<<<256, 512>>>(W1, (const int*)ei);

    // CSR build
    const int eblocks = (E + 511) / 512;
    hist_k<<<eblocks, 512>>>(ei, E, N);
    scan1_k<<<NPART, 512>>>();
    scan2_k<<<1, 256>>>();
    scan3_k<<<NPART, 512>>>();
    scatter_k<<<eblocks, 512>>>(ei, E, N);

    // GEMM
    const int nstrips = (N + MTILE - 1) / MTILE;
    gemm_tc<<<296, 512, SMEM_BYTES>>>(z, b1, N, nstrips);

    // CSR edge pass
    edge_csr<<<2048, 256>>>(W2, b2, out, E, N);
}

// round 12
// speedup vs baseline: 1.1467x; 1.1467x over previous
#include <cuda_runtime.h>
#include <cuda_fp16.h>
#include <cstdint>

// ---------------------------------------------------------------------------
// EdgeDecoder:
//   A'[n] = z[n] @ W1[0:128,:] + b1 ; B[n] = z[n] @ W1[128:256,:]
//   score[e] = relu(A'[src] + B[dst]) . W2 + b2
//
// R11 (resubmit after infra failure): edge kernel is LTS-capped (R4/R6
// measure ~9-11.5 TB/s L2). CSR-sort edges by src -> flat sorted entry list;
// edge kernel keeps R6's high-MLP structure (16 entries/warp, 8 unrolled
// iters) so consecutive entries share src: A-row re-reads hit L1 (not LTS).
// B gathers use ld.global.cg to keep L1 reserved for A rows.
// gemm/prep = R8 verbatim.
// ---------------------------------------------------------------------------

#define HID 128
#define N_MAX 100000
#define E_MAX 1600000
#define NS_PAD 100352            // 196 * 512
#define NPART 196

__device__ __align__(16) __half g_AB[(size_t)N_MAX * 256];
__device__ __align__(16) __half g_Whi[128 * 256];
__device__ int g_is64;
__device__ int g_hist[NS_PAD];
__device__ int g_rowstart[NS_PAD];
__device__ int g_cursor[NS_PAD];
__device__ int g_part[NPART];
__device__ __align__(16) uint4 g_slist[E_MAX];   // {aoff, boff, e, 0} sorted by src

// ---- tensor-core primitives ----
__device__ __forceinline__ void ldsm4(unsigned* r, const void* p) {
    unsigned a = (unsigned)__cvta_generic_to_shared(p);
    asm volatile("ldmatrix.sync.aligned.m8n8.x4.shared.b16 {%0,%1,%2,%3},[%4];"
                 : "=r"(r[0]), "=r"(r[1]), "=r"(r[2]), "=r"(r[3]) : "r"(a));
}
__device__ __forceinline__ void ldsm2t(unsigned* r, const void* p) {
    unsigned a = (unsigned)__cvta_generic_to_shared(p);
    asm volatile("ldmatrix.sync.aligned.m8n8.x2.trans.shared.b16 {%0,%1},[%2];"
                 : "=r"(r[0]), "=r"(r[1]) : "r"(a));
}
__device__ __forceinline__ void stsm4(void* p, unsigned r0, unsigned r1,
                                      unsigned r2, unsigned r3) {
    unsigned a = (unsigned)__cvta_generic_to_shared(p);
    asm volatile("stmatrix.sync.aligned.m8n8.x4.shared.b16 [%0],{%1,%2,%3,%4};"
                 :: "r"(a), "r"(r0), "r"(r1), "r"(r2), "r"(r3));
}
__device__ __forceinline__ void mma16816(float* c, const unsigned* a, const unsigned* b) {
    asm volatile(
        "mma.sync.aligned.m16n8k16.row.col.f32.f16.f16.f32 "
        "{%0,%1,%2,%3},{%4,%5,%6,%7},{%8,%9},{%0,%1,%2,%3};"
        : "+f"(c[0]), "+f"(c[1]), "+f"(c[2]), "+f"(c[3])
        : "r"(a[0]), "r"(a[1]), "r"(a[2]), "r"(a[3]), "r"(b[0]), "r"(b[1]));
}
// B-gather: L2-cached only (.cg) -> keeps L1 free for reused A rows
__device__ __forceinline__ uint4 ldg_cg_v4(const void* p) {
    uint4 v;
    asm volatile("ld.global.cg.v4.u32 {%0,%1,%2,%3},[%4];"
                 : "=r"(v.x), "=r"(v.y), "=r"(v.z), "=r"(v.w) : "l"(p));
    return v;
}

#define ZS 136
#define WS 264
#define OS 264
#define MTILE 64
#define SMEM_BYTES ((128 * WS + 2 * MTILE * ZS) * 2)   // 102,400 B

// ---------------------------------------------------------------------------
// Prep: W fp16 cvt + dtype probe + zero hist. grid 256 x 512.
// ---------------------------------------------------------------------------
__global__ __launch_bounds__(512) void prep_w(
    const float* __restrict__ W1, const int* __restrict__ ei32)
{
    int idx = blockIdx.x * 512 + threadIdx.x;
    if (blockIdx.x == 0 && threadIdx.x == 0) {
        int all0 = 1;
#pragma unroll
        for (int i = 0; i < 8; ++i) all0 &= (ei32[2 * i + 1] == 0);
        g_is64 = all0;
    }
    if (idx < 32768) {
        int k = idx >> 8, j = idx & 255;
        float f = (j < 128) ? W1[(size_t)k * 128 + j]
                            : W1[(size_t)(128 + k) * 128 + (j - 128)];
        g_Whi[idx] = __float2half_rn(f);
    }
    if (idx < NS_PAD) g_hist[idx] = 0;
}

// ---------------------------------------------------------------------------
// CSR build chain.
// ---------------------------------------------------------------------------
__global__ __launch_bounds__(512) void hist_k(
    const void* __restrict__ ei_raw, int E, int N)
{
    int e = blockIdx.x * 512 + threadIdx.x;
    if (e >= E) return;
    const int* p = (const int*)ei_raw;
    unsigned s = g_is64 ? (unsigned)p[2 * (size_t)e] : (unsigned)p[e];
    s = min(s, (unsigned)(N - 1));
    atomicAdd(&g_hist[s], 1);
}

__global__ __launch_bounds__(512) void scan1_k()
{
    __shared__ int sh[512];
    const int t = threadIdx.x;
    const int i = blockIdx.x * 512 + t;
    int v = g_hist[i];
    sh[t] = v;
    __syncthreads();
#pragma unroll
    for (int off = 1; off < 512; off <<= 1) {
        int x = sh[t];
        if (t >= off) x += sh[t - off];
        __syncthreads();
        sh[t] = x;
        __syncthreads();
    }
    g_rowstart[i] = sh[t] - v;
    if (t == 511) g_part[blockIdx.x] = sh[511];
}

__global__ __launch_bounds__(256) void scan2_k()
{
    __shared__ int sh[256];
    const int t = threadIdx.x;
    int v = (t < NPART) ? g_part[t] : 0;
    sh[t] = v;
    __syncthreads();
#pragma unroll
    for (int off = 1; off < 256; off <<= 1) {
        int x = sh[t];
        if (t >= off) x += sh[t - off];
        __syncthreads();
        sh[t] = x;
        __syncthreads();
    }
    if (t < NPART) g_part[t] = sh[t] - v;
}

__global__ __launch_bounds__(512) void scan3_k()
{
    const int i = blockIdx.x * 512 + threadIdx.x;
    int r = g_rowstart[i] + g_part[blockIdx.x];
    g_cursor[i] = r;
}

__global__ __launch_bounds__(512) void scatter_k(
    const void* __restrict__ ei_raw, int E, int N)
{
    int e = blockIdx.x * 512 + threadIdx.x;
    if (e >= E) return;
    const int* p = (const int*)ei_raw;
    unsigned s, d;
    if (g_is64) {
        s = (unsigned)p[2 * (size_t)e];
        d = (unsigned)p[2 * ((size_t)E + e)];
    } else {
        s = (unsigned)p[e];
        d = (unsigned)p[(size_t)E + e];
    }
    s = min(s, (unsigned)(N - 1));
    d = min(d, (unsigned)(N - 1));
    int pos = atomicAdd(&g_cursor[s], 1);
    g_slist[pos] = make_uint4(s * 256u, d * 256u + 128u, (unsigned)e, 0u);
}

// ---------------------------------------------------------------------------
// Persistent GEMM (R8 verbatim): M-tile 64, 2 CTAs/SM, 2-term compensated.
// ---------------------------------------------------------------------------
__global__ __launch_bounds__(512, 2) void gemm_tc(
    const float* __restrict__ z, const float* __restrict__ b1,
    int N, int nstrips)
{
    extern __shared__ __align__(16) char dynsmem[];
    __half* Whi = (__half*)dynsmem;
    __half* Zhi = Whi + 128 * WS;
    __half* Zlo = Zhi + MTILE * ZS;
    __half* Stage = Zhi;

    const int t    = threadIdx.x;
    const int lane = t & 31;
    const int w    = t >> 5;

#pragma unroll
    for (int i = 0; i < 8; ++i) {
        int idx = t + i * 512;
        int row = idx >> 5, c16 = idx & 31;
        *(uint4*)&Whi[row * WS + c16 * 8] = *(const uint4*)&g_Whi[row * 256 + c16 * 8];
    }
    __syncthreads();

    const int wm = w >> 3, wn = w & 7;
    const int mbase = wm * 32, nbase = wn * 32;
    const int arow = lane & 15, acol8 = (lane >> 4) << 3;
    const int brow = lane & 15;

    float bx[4], by[4];
#pragma unroll
    for (int nt = 0; nt < 4; ++nt) {
        int col = nbase + nt * 8 + (lane & 3) * 2;
        bx[nt] = (wn < 4) ? __ldg(b1 + col)     : 0.f;
        by[nt] = (wn < 4) ? __ldg(b1 + col + 1) : 0.f;
    }

    for (int strip = blockIdx.x; strip < nstrips; strip += gridDim.x) {
        const int row0 = strip * MTILE;

#pragma unroll
        for (int i = 0; i < 4; ++i) {
            int idx4 = t + i * 512;
            int r = idx4 >> 5, c = (idx4 & 31) * 4;
            int gr = row0 + r; if (gr >= N) gr = N - 1;
            float4 v = *(const float4*)(z + (size_t)gr * HID + c);
            __half2 h0 = __floats2half2_rn(v.x, v.y);
            __half2 h1 = __floats2half2_rn(v.z, v.w);
            float2 f0 = __half22float2(h0), f1 = __half22float2(h1);
            __half2 l0 = __floats2half2_rn(v.x - f0.x, v.y - f0.y);
            __half2 l1 = __floats2half2_rn(v.z - f1.x, v.w - f1.y);
            uint2 sh, sl;
            sh.x = *(unsigned*)&h0; sh.y = *(unsigned*)&h1;
            sl.x = *(unsigned*)&l0; sl.y = *(unsigned*)&l1;
            *(uint2*)&Zhi[r * ZS + c] = sh;
            *(uint2*)&Zlo[r * ZS + c] = sl;
        }
        __syncthreads();

        float acc[2][4][4];
#pragma unroll
        for (int mt = 0; mt < 2; ++mt)
#pragma unroll
            for (int nt = 0; nt < 4; ++nt)
#pragma unroll
                for (int q = 0; q < 4; ++q) acc[mt][nt][q] = 0.f;

#pragma unroll
        for (int ks = 0; ks < 8; ++ks) {
            const int k0 = ks * 16;
            unsigned ah[2][4], al[2][4];
#pragma unroll
            for (int mt = 0; mt < 2; ++mt) {
                const int rr = (mbase + mt * 16 + arow) * ZS + k0 + acol8;
                ldsm4(ah[mt], Zhi + rr);
                ldsm4(al[mt], Zlo + rr);
            }
#pragma unroll
            for (int nt = 0; nt < 4; ++nt) {
                unsigned bb[2];
                const int wr = (k0 + brow) * WS + nbase + nt * 8;
                ldsm2t(bb, Whi + wr);
#pragma unroll
                for (int mt = 0; mt < 2; ++mt) {
                    mma16816(acc[mt][nt], ah[mt], bb);
                    mma16816(acc[mt][nt], al[mt], bb);
                }
            }
        }
        __syncthreads();

        const int stile = lane >> 3;
        const int srow  = lane & 7;
#pragma unroll
        for (int mt = 0; mt < 2; ++mt) {
            __half2 u[4], l[4];
#pragma unroll
            for (int nt = 0; nt < 4; ++nt) {
                u[nt] = __floats2half2_rn(acc[mt][nt][0] + bx[nt], acc[mt][nt][1] + by[nt]);
                l[nt] = __floats2half2_rn(acc[mt][nt][2] + bx[nt], acc[mt][nt][3] + by[nt]);
            }
            __half* pu = Stage + (mbase + mt * 16 + srow) * OS + nbase + stile * 8;
            __half* pl = Stage + (mbase + mt * 16 + 8 + srow) * OS + nbase + stile * 8;
            stsm4(pu, *(unsigned*)&u[0], *(unsigned*)&u[1], *(unsigned*)&u[2], *(unsigned*)&u[3]);
            stsm4(pl, *(unsigned*)&l[0], *(unsigned*)&l[1], *(unsigned*)&l[2], *(unsigned*)&l[3]);
        }
        __syncthreads();

#pragma unroll
        for (int i = 0; i < 4; ++i) {
            int idx = t + i * 512;
            int r = idx >> 5, c16 = idx & 31;
            int gr = row0 + r;
            if (gr < N) {
                uint4 v = *(const uint4*)&Stage[r * OS + c16 * 8];
                *(uint4*)&g_AB[(size_t)gr * 256 + c16 * 8] = v;
            }
        }
        __syncthreads();
    }
}

// ---------------------------------------------------------------------------
// Edge kernel: R6 structure over the SORTED entry list.
// 16 lanes/edge, 2 edges/warp-iter, 8 iters. A via L1 (.ca), B via .cg.
// ---------------------------------------------------------------------------
#define EDGE_ITER 8

__global__ __launch_bounds__(256) void edge_sorted(
    const float* __restrict__ W2,
    const float* __restrict__ b2,
    float* __restrict__ out,
    int E)
{
    const int lane = threadIdx.x & 31;
    const int gl   = lane & 15;
    const int hi16 = lane >> 4;
    const int warp = threadIdx.x >> 5;
    const int ebase = (blockIdx.x * 8 + warp) * (2 * EDGE_ITER) + hi16;

    const float4 wwl = *(const float4*)(W2 + gl * 8);
    const float4 wwh = *(const float4*)(W2 + gl * 8 + 4);
    const float wwf[8] = {wwl.x, wwl.y, wwl.z, wwl.w, wwh.x, wwh.y, wwh.z, wwh.w};
    const float bias2 = __ldg(b2);
    const __half2 zero2 = __float2half2_rn(0.f);

#pragma unroll
    for (int it = 0; it < EDGE_ITER; ++it) {
        const int e = ebase + it * 2;
        if (e >= E) return;

        const uint4 ent = __ldg(&g_slist[e]);   // broadcast within 16-lane group

        // A: default .ca — consecutive sorted entries share src -> L1 hits
        const uint4 ar = *(const uint4*)(g_AB + ent.x + gl * 8);
        // B: .cg — random, zero-reuse; keep it out of L1
        const uint4 br = ldg_cg_v4(g_AB + ent.y + gl * 8);

        const unsigned* au = (const unsigned*)&ar;
        const unsigned* bu = (const unsigned*)&br;

        float sum = 0.f;
#pragma unroll
        for (int i = 0; i < 4; ++i) {
            __half2 r = __hmax2(__hadd2(*(const __half2*)&au[i],
                                        *(const __half2*)&bu[i]), zero2);
            float2 f = __half22float2(r);
            sum = fmaf(f.x, wwf[2 * i],     sum);
            sum = fmaf(f.y, wwf[2 * i + 1], sum);
        }
#pragma unroll
        for (int off = 8; off; off >>= 1)
            sum += __shfl_xor_sync(0xFFFFFFFFu, sum, off);

        if (gl == 0)
            out[ent.z] = sum + bias2;
    }
}

// ---------------------------------------------------------------------------
extern "C" void kernel_launch(void* const* d_in, const int* in_sizes, int n_in,
                              void* d_out, int out_size)
{
    const float* z   = (const float*)d_in[0];
    const void*  ei  = d_in[1];
    const float* W1  = (const float*)d_in[2];
    const float* b1  = (const float*)d_in[3];
    const float* W2  = (const float*)d_in[4];
    const float* b2  = (const float*)d_in[5];
    float*       out = (float*)d_out;

    const int N = in_sizes[0] / HID;   // 100000
    const int E = in_sizes[1] / 2;     // 1600000

    static int smem_set = 0;
    if (!smem_set) {
        cudaFuncSetAttribute(gemm_tc, cudaFuncAttributeMaxDynamicSharedMemorySize,
                             SMEM_BYTES);
        smem_set = 1;
    }

    prep_w<<<256, 512>>>(W1, (const int*)ei);

    const int eblocks = (E + 511) / 512;
    hist_k<<<eblocks, 512>>>(ei, E, N);
    scan1_k<<<NPART, 512>>>();
    scan2_k<<<1, 256>>>();
    scan3_k<<<NPART, 512>>>();
    scatter_k<<<eblocks, 512>>>(ei, E, N);

    const int nstrips = (N + MTILE - 1) / MTILE;
    gemm_tc<<<296, 512, SMEM_BYTES>>>(z, b1, N, nstrips);

    const int edges_per_block = 8 * 2 * EDGE_ITER;   // 128
    edge_sorted<<<(E + edges_per_block - 1) / edges_per_block, 256>>>(
        W2, b2, out, E);
}

// round 13
// speedup vs baseline: 1.6785x; 1.4637x over previous
#include <cuda_runtime.h>
#include <cuda_fp16.h>
#include <cstdint>

// ---------------------------------------------------------------------------
// EdgeDecoder:
//   A'[n] = z[n] @ W1[0:128,:] + b1 ; B[n] = z[n] @ W1[128:256,:]
//   score[e] = relu(A'[src] + B[dst]) . W2 + b2
//
// R13: after four failed edge restructures, accept the R6 edge kernel as the
// LTS-floor configuration (~845MB @ ~11.5TB/s). Remove fixed overhead:
// prep merged into gemm (per-block W1 fp32->fp16 convert straight into smem,
// block-0 dtype probe) -> 2 launches total. gemm/edge otherwise R8 verbatim.
// ---------------------------------------------------------------------------

#define HID 128
#define N_MAX 100000

__device__ __align__(16) __half g_AB[(size_t)N_MAX * 256];
__device__ int g_is64;

// ---- tensor-core primitives ----
__device__ __forceinline__ void ldsm4(unsigned* r, const void* p) {
    unsigned a = (unsigned)__cvta_generic_to_shared(p);
    asm volatile("ldmatrix.sync.aligned.m8n8.x4.shared.b16 {%0,%1,%2,%3},[%4];"
                 : "=r"(r[0]), "=r"(r[1]), "=r"(r[2]), "=r"(r[3]) : "r"(a));
}
__device__ __forceinline__ void ldsm2t(unsigned* r, const void* p) {
    unsigned a = (unsigned)__cvta_generic_to_shared(p);
    asm volatile("ldmatrix.sync.aligned.m8n8.x2.trans.shared.b16 {%0,%1},[%2];"
                 : "=r"(r[0]), "=r"(r[1]) : "r"(a));
}
__device__ __forceinline__ void stsm4(void* p, unsigned r0, unsigned r1,
                                      unsigned r2, unsigned r3) {
    unsigned a = (unsigned)__cvta_generic_to_shared(p);
    asm volatile("stmatrix.sync.aligned.m8n8.x4.shared.b16 [%0],{%1,%2,%3,%4};"
                 :: "r"(a), "r"(r0), "r"(r1), "r"(r2), "r"(r3));
}
__device__ __forceinline__ void mma16816(float* c, const unsigned* a, const unsigned* b) {
    asm volatile(
        "mma.sync.aligned.m16n8k16.row.col.f32.f16.f16.f32 "
        "{%0,%1,%2,%3},{%4,%5,%6,%7},{%8,%9},{%0,%1,%2,%3};"
        : "+f"(c[0]), "+f"(c[1]), "+f"(c[2]), "+f"(c[3])
        : "r"(a[0]), "r"(a[1]), "r"(a[2]), "r"(a[3]), "r"(b[0]), "r"(b[1]));
}

// smem strides in halves; row byte strides 272/528 -> 16B shift/row, conflict-free
#define ZS 136
#define WS 264
#define OS 264
#define MTILE 64
#define SMEM_BYTES ((128 * WS + 2 * MTILE * ZS) * 2)   // 102,400 B -> 2 CTAs/SM

// ---------------------------------------------------------------------------
// Persistent GEMM (R8 structure) with in-kernel W conversion + dtype probe.
// ---------------------------------------------------------------------------
__global__ __launch_bounds__(512, 2) void gemm_tc(
    const float* __restrict__ z,    // [N,128]
    const float* __restrict__ W1,   // [256,128] fp32
    const float* __restrict__ b1,   // [128]
    const int*   __restrict__ ei32, // edge_index viewed as int32 (probe)
    int N, int nstrips)
{
    extern __shared__ __align__(16) char dynsmem[];
    __half* Whi = (__half*)dynsmem;            // [128][WS]
    __half* Zhi = Whi + 128 * WS;              // [MTILE][ZS]
    __half* Zlo = Zhi + MTILE * ZS;
    __half* Stage = Zhi;                       // overlay [MTILE][OS]

    const int t    = threadIdx.x;
    const int lane = t & 31;
    const int w    = t >> 5;

    // dtype probe (consumed only by the edge kernel, after this kernel ends)
    if (blockIdx.x == 0 && t == 0) {
        int all0 = 1;
#pragma unroll
        for (int i = 0; i < 8; ++i) all0 &= (ei32[2 * i + 1] == 0);
        g_is64 = all0;
    }

    // ---- W1 fp32 -> fused fp16 layout in smem ----
    // fused: Whi[k][j] = (j<128) ? W1[k][j] : W1[128+k][j-128]
    // Read W1 linearly (coalesced float4); derive the fused destination.
#pragma unroll
    for (int i = 0; i < 16; ++i) {
        int f4 = t + i * 512;                  // 0..8191 float4 index
        int kp = f4 >> 5;                      // source row 0..255
        int jp = (f4 & 31) * 4;                // source col 0..124
        float4 v = *(const float4*)(W1 + kp * 128 + jp);
        int k   = (kp < 128) ? kp : kp - 128;
        int col = (kp < 128) ? jp : jp + 128;
        __half2 h0 = __floats2half2_rn(v.x, v.y);
        __half2 h1 = __floats2half2_rn(v.z, v.w);
        uint2 s; s.x = *(unsigned*)&h0; s.y = *(unsigned*)&h1;
        *(uint2*)&Whi[k * WS + col] = s;
    }
    __syncthreads();

    const int wm = w >> 3, wn = w & 7;         // 2 x 8 warps
    const int mbase = wm * 32, nbase = wn * 32;
    const int arow = lane & 15, acol8 = (lane >> 4) << 3;
    const int brow = lane & 15;

    float bx[4], by[4];
#pragma unroll
    for (int nt = 0; nt < 4; ++nt) {
        int col = nbase + nt * 8 + (lane & 3) * 2;
        bx[nt] = (wn < 4) ? __ldg(b1 + col)     : 0.f;
        by[nt] = (wn < 4) ? __ldg(b1 + col + 1) : 0.f;
    }

    for (int strip = blockIdx.x; strip < nstrips; strip += gridDim.x) {
        const int row0 = strip * MTILE;

        // ---- Z fill: fp32 -> fp16 hi/lo ----
#pragma unroll
        for (int i = 0; i < 4; ++i) {
            int idx4 = t + i * 512;
            int r = idx4 >> 5, c = (idx4 & 31) * 4;
            int gr = row0 + r; if (gr >= N) gr = N - 1;
            float4 v = *(const float4*)(z + (size_t)gr * HID + c);
            __half2 h0 = __floats2half2_rn(v.x, v.y);
            __half2 h1 = __floats2half2_rn(v.z, v.w);
            float2 f0 = __half22float2(h0), f1 = __half22float2(h1);
            __half2 l0 = __floats2half2_rn(v.x - f0.x, v.y - f0.y);
            __half2 l1 = __floats2half2_rn(v.z - f1.x, v.w - f1.y);
            uint2 sh, sl;
            sh.x = *(unsigned*)&h0; sh.y = *(unsigned*)&h1;
            sl.x = *(unsigned*)&l0; sl.y = *(unsigned*)&l1;
            *(uint2*)&Zhi[r * ZS + c] = sh;
            *(uint2*)&Zlo[r * ZS + c] = sl;
        }
        __syncthreads();

        // ---- compute: Ah*Bh + Al*Bh, fp32 acc; warp tile 32x32 ----
        float acc[2][4][4];
#pragma unroll
        for (int mt = 0; mt < 2; ++mt)
#pragma unroll
            for (int nt = 0; nt < 4; ++nt)
#pragma unroll
                for (int q = 0; q < 4; ++q) acc[mt][nt][q] = 0.f;

#pragma unroll
        for (int ks = 0; ks < 8; ++ks) {
            const int k0 = ks * 16;
            unsigned ah[2][4], al[2][4];
#pragma unroll
            for (int mt = 0; mt < 2; ++mt) {
                const int rr = (mbase + mt * 16 + arow) * ZS + k0 + acol8;
                ldsm4(ah[mt], Zhi + rr);
                ldsm4(al[mt], Zlo + rr);
            }
#pragma unroll
            for (int nt = 0; nt < 4; ++nt) {
                unsigned bb[2];
                const int wr = (k0 + brow) * WS + nbase + nt * 8;
                ldsm2t(bb, Whi + wr);
#pragma unroll
                for (int mt = 0; mt < 2; ++mt) {
                    mma16816(acc[mt][nt], ah[mt], bb);
                    mma16816(acc[mt][nt], al[mt], bb);
                }
            }
        }
        __syncthreads();   // all warps done reading Z before Stage overwrite

        // ---- stmatrix epilogue into Stage ----
        const int stile = lane >> 3;
        const int srow  = lane & 7;
#pragma unroll
        for (int mt = 0; mt < 2; ++mt) {
            __half2 u[4], l[4];
#pragma unroll
            for (int nt = 0; nt < 4; ++nt) {
                u[nt] = __floats2half2_rn(acc[mt][nt][0] + bx[nt], acc[mt][nt][1] + by[nt]);
                l[nt] = __floats2half2_rn(acc[mt][nt][2] + bx[nt], acc[mt][nt][3] + by[nt]);
            }
            __half* pu = Stage + (mbase + mt * 16 + srow) * OS + nbase + stile * 8;
            __half* pl = Stage + (mbase + mt * 16 + 8 + srow) * OS + nbase + stile * 8;
            stsm4(pu, *(unsigned*)&u[0], *(unsigned*)&u[1], *(unsigned*)&u[2], *(unsigned*)&u[3]);
            stsm4(pl, *(unsigned*)&l[0], *(unsigned*)&l[1], *(unsigned*)&l[2], *(unsigned*)&l[3]);
        }
        __syncthreads();

        // ---- coalesced copy Stage -> g_AB ----
#pragma unroll
        for (int i = 0; i < 4; ++i) {
            int idx = t + i * 512;
            int r = idx >> 5, c16 = idx & 31;
            int gr = row0 + r;
            if (gr < N) {
                uint4 v = *(const uint4*)&Stage[r * OS + c16 * 8];
                *(uint4*)&g_AB[(size_t)gr * 256 + c16 * 8] = v;
            }
        }
        __syncthreads();
    }
}

// ---------------------------------------------------------------------------
// Edge kernel (R6/R8 verbatim): 16 lanes/edge, 2 edges/warp, 8 iters;
// half2 add/relu, fp32 dot.
// ---------------------------------------------------------------------------
#define EDGE_ITER 8

__global__ __launch_bounds__(256) void edge_score(
    const void* __restrict__ ei_raw,
    const float* __restrict__ W2,
    const float* __restrict__ b2,
    float* __restrict__ out,
    int E, int N)
{
    const int lane = threadIdx.x & 31;
    const int gl   = lane & 15;
    const int warp = threadIdx.x >> 5;
    const int ebase = (blockIdx.x * 8 + warp) * (2 * EDGE_ITER) + (lane >> 4);

    const float4 wwl = *(const float4*)(W2 + gl * 8);
    const float4 wwh = *(const float4*)(W2 + gl * 8 + 4);
    const float wwf[8] = {wwl.x, wwl.y, wwl.z, wwl.w, wwh.x, wwh.y, wwh.z, wwh.w};
    const float bias2 = __ldg(b2);
    const int is64 = g_is64;
    const __half2 zero2 = __float2half2_rn(0.f);

#pragma unroll
    for (int it = 0; it < EDGE_ITER; ++it) {
        const int e = ebase + it * 2;
        if (e >= E) return;

        unsigned s, d;
        if (is64) {
            const long long* ei = (const long long*)ei_raw;
            s = (unsigned)ei[e];
            d = (unsigned)ei[(size_t)E + e];
        } else {
            const int* ei = (const int*)ei_raw;
            s = (unsigned)ei[e];
            d = (unsigned)ei[(size_t)E + e];
        }
        s = min(s, (unsigned)(N - 1));
        d = min(d, (unsigned)(N - 1));

        const uint4 ar = *(const uint4*)(g_AB + (size_t)s * 256 + gl * 8);
        const uint4 br = *(const uint4*)(g_AB + (size_t)d * 256 + 128 + gl * 8);
        const unsigned* au = (const unsigned*)&ar;
        const unsigned* bu = (const unsigned*)&br;

        float sum = 0.f;
#pragma unroll
        for (int i = 0; i < 4; ++i) {
            __half2 r = __hmax2(__hadd2(*(const __half2*)&au[i],
                                        *(const __half2*)&bu[i]), zero2);
            float2 f = __half22float2(r);
            sum = fmaf(f.x, wwf[2 * i],     sum);
            sum = fmaf(f.y, wwf[2 * i + 1], sum);
        }
#pragma unroll
        for (int off = 8; off; off >>= 1)
            sum += __shfl_xor_sync(0xFFFFFFFFu, sum, off);

        if (gl == 0)
            out[e] = sum + bias2;
    }
}

// ---------------------------------------------------------------------------
extern "C" void kernel_launch(void* const* d_in, const int* in_sizes, int n_in,
                              void* d_out, int out_size)
{
    const float* z   = (const float*)d_in[0];
    const void*  ei  = d_in[1];
    const float* W1  = (const float*)d_in[2];
    const float* b1  = (const float*)d_in[3];
    const float* W2  = (const float*)d_in[4];
    const float* b2  = (const float*)d_in[5];
    float*       out = (float*)d_out;

    const int N = in_sizes[0] / HID;   // 100000
    const int E = in_sizes[1] / 2;     // 1600000

    static int smem_set = 0;
    if (!smem_set) {
        cudaFuncSetAttribute(gemm_tc, cudaFuncAttributeMaxDynamicSharedMemorySize,
                             SMEM_BYTES);
        smem_set = 1;
    }

    const int nstrips = (N + MTILE - 1) / MTILE;       // 1563
    gemm_tc<<<296, 512, SMEM_BYTES>>>(z, W1, b1, (const int*)ei, N, nstrips);

    const int edges_per_block = 8 * 2 * EDGE_ITER;     // 128
    edge_score<<<(E + edges_per_block - 1) / edges_per_block, 256>>>(
        ei, W2, b2, out, E, N);
}

// round 14
// speedup vs baseline: 1.9593x; 1.1673x over previous
#include <cuda_runtime.h>
#include <cuda_fp16.h>
#include <cstdint>

// ---------------------------------------------------------------------------
// EdgeDecoder:
//   A'[n] = z[n] @ W1[0:128,:] + b1 ; B[n] = z[n] @ W1[128:256,:]
//   score[e] = relu(A'[src] + B[dst]) . W2 + b2
//
// R14: single-term fp16 HMMA gemm (drop Al*Bh z-compensation). Error ledger
// (all measured, quadrature): storage 2.48e-4 + edge-hadd2 2.7e-4 +
// W-quant 2.1e-4 = 4.24e-4; z-quant adds ~2.5e-4 -> ~4.9e-4 predicted.
// MMA count halves (the dominant gemm cost); Zlo fill removed; smem 101KB.
// Edge kernel: R13 verbatim (L1tex-bound floor ~66us).
// Launches: 2 (W-convert + dtype probe inside gemm).
// ---------------------------------------------------------------------------

#define HID 128
#define N_MAX 100000

__device__ __align__(16) __half g_AB[(size_t)N_MAX * 256];
__device__ int g_is64;

// ---- tensor-core primitives ----
__device__ __forceinline__ void ldsm4(unsigned* r, const void* p) {
    unsigned a = (unsigned)__cvta_generic_to_shared(p);
    asm volatile("ldmatrix.sync.aligned.m8n8.x4.shared.b16 {%0,%1,%2,%3},[%4];"
                 : "=r"(r[0]), "=r"(r[1]), "=r"(r[2]), "=r"(r[3]) : "r"(a));
}
__device__ __forceinline__ void ldsm2t(unsigned* r, const void* p) {
    unsigned a = (unsigned)__cvta_generic_to_shared(p);
    asm volatile("ldmatrix.sync.aligned.m8n8.x2.trans.shared.b16 {%0,%1},[%2];"
                 : "=r"(r[0]), "=r"(r[1]) : "r"(a));
}
__device__ __forceinline__ void stsm4(void* p, unsigned r0, unsigned r1,
                                      unsigned r2, unsigned r3) {
    unsigned a = (unsigned)__cvta_generic_to_shared(p);
    asm volatile("stmatrix.sync.aligned.m8n8.x4.shared.b16 [%0],{%1,%2,%3,%4};"
                 :: "r"(a), "r"(r0), "r"(r1), "r"(r2), "r"(r3));
}
__device__ __forceinline__ void mma16816(float* c, const unsigned* a, const unsigned* b) {
    asm volatile(
        "mma.sync.aligned.m16n8k16.row.col.f32.f16.f16.f32 "
        "{%0,%1,%2,%3},{%4,%5,%6,%7},{%8,%9},{%0,%1,%2,%3};"
        : "+f"(c[0]), "+f"(c[1]), "+f"(c[2]), "+f"(c[3])
        : "r"(a[0]), "r"(a[1]), "r"(a[2]), "r"(a[3]), "r"(b[0]), "r"(b[1]));
}

// smem strides in halves; row byte strides 272/528 -> conflict-free ldmatrix
#define ZS 136
#define WS 264
#define OS 264
#define MTILE 64
// W [128][WS] + Stage [MTILE][OS] (Z [MTILE][ZS] overlays Stage's front)
#define SMEM_BYTES ((128 * WS + MTILE * OS) * 2)   // 101,376 B -> 2 CTAs/SM

// ---------------------------------------------------------------------------
// Persistent GEMM, single-term fp16, in-kernel W convert + dtype probe.
// ---------------------------------------------------------------------------
__global__ __launch_bounds__(512, 2) void gemm_tc(
    const float* __restrict__ z,    // [N,128]
    const float* __restrict__ W1,   // [256,128] fp32
    const float* __restrict__ b1,   // [128]
    const int*   __restrict__ ei32, // edge_index viewed as int32 (probe)
    int N, int nstrips)
{
    extern __shared__ __align__(16) char dynsmem[];
    __half* Whi   = (__half*)dynsmem;          // [128][WS]
    __half* Stage = Whi + 128 * WS;            // [MTILE][OS]
    __half* Zhi   = Stage;                     // [MTILE][ZS] overlays Stage

    const int t    = threadIdx.x;
    const int lane = t & 31;
    const int w    = t >> 5;

    // dtype probe (consumed only by the edge kernel, after this kernel ends)
    if (blockIdx.x == 0 && t == 0) {
        int all0 = 1;
#pragma unroll
        for (int i = 0; i < 8; ++i) all0 &= (ei32[2 * i + 1] == 0);
        g_is64 = all0;
    }

    // ---- W1 fp32 -> fused fp16 layout in smem ----
    // fused: Whi[k][j] = (j<128) ? W1[k][j] : W1[128+k][j-128]
#pragma unroll
    for (int i = 0; i < 16; ++i) {
        int f4 = t + i * 512;                  // 0..8191 float4 index
        int kp = f4 >> 5;                      // source row 0..255
        int jp = (f4 & 31) * 4;                // source col 0..124
        float4 v = *(const float4*)(W1 + kp * 128 + jp);
        int k   = (kp < 128) ? kp : kp - 128;
        int col = (kp < 128) ? jp : jp + 128;
        __half2 h0 = __floats2half2_rn(v.x, v.y);
        __half2 h1 = __floats2half2_rn(v.z, v.w);
        uint2 s; s.x = *(unsigned*)&h0; s.y = *(unsigned*)&h1;
        *(uint2*)&Whi[k * WS + col] = s;
    }
    __syncthreads();

    const int wm = w >> 3, wn = w & 7;         // 2 x 8 warps
    const int mbase = wm * 32, nbase = wn * 32;
    const int arow = lane & 15, acol8 = (lane >> 4) << 3;
    const int brow = lane & 15;

    float bx[4], by[4];
#pragma unroll
    for (int nt = 0; nt < 4; ++nt) {
        int col = nbase + nt * 8 + (lane & 3) * 2;
        bx[nt] = (wn < 4) ? __ldg(b1 + col)     : 0.f;
        by[nt] = (wn < 4) ? __ldg(b1 + col + 1) : 0.f;
    }

    for (int strip = blockIdx.x; strip < nstrips; strip += gridDim.x) {
        const int row0 = strip * MTILE;

        // ---- Z fill: fp32 -> fp16 (single) ----
#pragma unroll
        for (int i = 0; i < 4; ++i) {
            int idx4 = t + i * 512;            // 0..2047 float4s
            int r = idx4 >> 5, c = (idx4 & 31) * 4;
            int gr = row0 + r; if (gr >= N) gr = N - 1;
            float4 v = *(const float4*)(z + (size_t)gr * HID + c);
            __half2 h0 = __floats2half2_rn(v.x, v.y);
            __half2 h1 = __floats2half2_rn(v.z, v.w);
            uint2 sh; sh.x = *(unsigned*)&h0; sh.y = *(unsigned*)&h1;
            *(uint2*)&Zhi[r * ZS + c] = sh;
        }
        __syncthreads();

        // ---- compute: Ah*Bh, fp32 acc; warp tile 32x32 ----
        float acc[2][4][4];
#pragma unroll
        for (int mt = 0; mt < 2; ++mt)
#pragma unroll
            for (int nt = 0; nt < 4; ++nt)
#pragma unroll
                for (int q = 0; q < 4; ++q) acc[mt][nt][q] = 0.f;

#pragma unroll
        for (int ks = 0; ks < 8; ++ks) {
            const int k0 = ks * 16;
            unsigned ah[2][4];
#pragma unroll
            for (int mt = 0; mt < 2; ++mt) {
                const int rr = (mbase + mt * 16 + arow) * ZS + k0 + acol8;
                ldsm4(ah[mt], Zhi + rr);
            }
#pragma unroll
            for (int nt = 0; nt < 4; ++nt) {
                unsigned bb[2];
                const int wr = (k0 + brow) * WS + nbase + nt * 8;
                ldsm2t(bb, Whi + wr);
#pragma unroll
                for (int mt = 0; mt < 2; ++mt)
                    mma16816(acc[mt][nt], ah[mt], bb);
            }
        }
        __syncthreads();   // all warps done reading Z before Stage overwrite

        // ---- stmatrix epilogue into Stage ----
        const int stile = lane >> 3;
        const int srow  = lane & 7;
#pragma unroll
        for (int mt = 0; mt < 2; ++mt) {
            __half2 u[4], l[4];
#pragma unroll
            for (int nt = 0; nt < 4; ++nt) {
                u[nt] = __floats2half2_rn(acc[mt][nt][0] + bx[nt], acc[mt][nt][1] + by[nt]);
                l[nt] = __floats2half2_rn(acc[mt][nt][2] + bx[nt], acc[mt][nt][3] + by[nt]);
            }
            __half* pu = Stage + (mbase + mt * 16 + srow) * OS + nbase + stile * 8;
            __half* pl = Stage + (mbase + mt * 16 + 8 + srow) * OS + nbase + stile * 8;
            stsm4(pu, *(unsigned*)&u[0], *(unsigned*)&u[1], *(unsigned*)&u[2], *(unsigned*)&u[3]);
            stsm4(pl, *(unsigned*)&l[0], *(unsigned*)&l[1], *(unsigned*)&l[2], *(unsigned*)&l[3]);
        }
        __syncthreads();

        // ---- coalesced copy Stage -> g_AB ----
#pragma unroll
        for (int i = 0; i < 4; ++i) {
            int idx = t + i * 512;             // 0..2047 uint4s
            int r = idx >> 5, c16 = idx & 31;
            int gr = row0 + r;
            if (gr < N) {
                uint4 v = *(const uint4*)&Stage[r * OS + c16 * 8];
                *(uint4*)&g_AB[(size_t)gr * 256 + c16 * 8] = v;
            }
        }
        __syncthreads();   // copy done before next strip's Z fill reuses area
    }
}

// ---------------------------------------------------------------------------
// Edge kernel (R13 verbatim): 16 lanes/edge, 2 edges/warp, 8 iters;
// half2 add/relu, fp32 dot.
// ---------------------------------------------------------------------------
#define EDGE_ITER 8

__global__ __launch_bounds__(256) void edge_score(
    const void* __restrict__ ei_raw,
    const float* __restrict__ W2,
    const float* __restrict__ b2,
    float* __restrict__ out,
    int E, int N)
{
    const int lane = threadIdx.x & 31;
    const int gl   = lane & 15;
    const int warp = threadIdx.x >> 5;
    const int ebase = (blockIdx.x * 8 + warp) * (2 * EDGE_ITER) + (lane >> 4);

    const float4 wwl = *(const float4*)(W2 + gl * 8);
    const float4 wwh = *(const float4*)(W2 + gl * 8 + 4);
    const float wwf[8] = {wwl.x, wwl.y, wwl.z, wwl.w, wwh.x, wwh.y, wwh.z, wwh.w};
    const float bias2 = __ldg(b2);
    const int is64 = g_is64;
    const __half2 zero2 = __float2half2_rn(0.f);

#pragma unroll
    for (int it = 0; it < EDGE_ITER; ++it) {
        const int e = ebase + it * 2;
        if (e >= E) return;

        unsigned s, d;
        if (is64) {
            const long long* ei = (const long long*)ei_raw;
            s = (unsigned)ei[e];
            d = (unsigned)ei[(size_t)E + e];
        } else {
            const int* ei = (const int*)ei_raw;
            s = (unsigned)ei[e];
            d = (unsigned)ei[(size_t)E + e];
        }
        s = min(s, (unsigned)(N - 1));
        d = min(d, (unsigned)(N - 1));

        const uint4 ar = *(const uint4*)(g_AB + (size_t)s * 256 + gl * 8);
        const uint4 br = *(const uint4*)(g_AB + (size_t)d * 256 + 128 + gl * 8);
        const unsigned* au = (const unsigned*)&ar;
        const unsigned* bu = (const unsigned*)&br;

        float sum = 0.f;
#pragma unroll
        for (int i = 0; i < 4; ++i) {
            __half2 r = __hmax2(__hadd2(*(const __half2*)&au[i],
                                        *(const __half2*)&bu[i]), zero2);
            float2 f = __half22float2(r);
            sum = fmaf(f.x, wwf[2 * i],     sum);
            sum = fmaf(f.y, wwf[2 * i + 1], sum);
        }
#pragma unroll
        for (int off = 8; off; off >>= 1)
            sum += __shfl_xor_sync(0xFFFFFFFFu, sum, off);

        if (gl == 0)
            out[e] = sum + bias2;
    }
}

// ---------------------------------------------------------------------------
extern "C" void kernel_launch(void* const* d_in, const int* in_sizes, int n_in,
                              void* d_out, int out_size)
{
    const float* z   = (const float*)d_in[0];
    const void*  ei  = d_in[1];
    const float* W1  = (const float*)d_in[2];
    const float* b1  = (const float*)d_in[3];
    const float* W2  = (const float*)d_in[4];
    const float* b2  = (const float*)d_in[5];
    float*       out = (float*)d_out;

    const int N = in_sizes[0] / HID;   // 100000
    const int E = in_sizes[1] / 2;     // 1600000

    static int smem_set = 0;
    if (!smem_set) {
        cudaFuncSetAttribute(gemm_tc, cudaFuncAttributeMaxDynamicSharedMemorySize,
                             SMEM_BYTES);
        smem_set = 1;
    }

    const int nstrips = (N + MTILE - 1) / MTILE;       // 1563
    gemm_tc<<<296, 512, SMEM_BYTES>>>(z, W1, b1, (const int*)ei, N, nstrips);

    const int edges_per_block = 8 * 2 * EDGE_ITER;     // 128
    edge_score<<<(E + edges_per_block - 1) / edges_per_block, 256>>>(
        ei, W2, b2, out, E, N);
}